// round 3
// baseline (speedup 1.0000x reference)
#include <cuda_runtime.h>
#include <cstdint>

// Problem constants (fixed by setup_inputs)
#define BATCH    32
#define CH       2
#define HH       480
#define WW       864
#define IGNORE_L 255
#define HWPLANE  (HH * WW)          // 414720

#define RADIUS   7
#define TX       288                // 9 payload words, W = 3 tiles exactly
#define TY       96                 // H = 5 tiles exactly
#define PW       9                  // payload words
#define IN_WORDS 11                 // 1 halo word each side
#define IN_ROWS  (TY + 2 * RADIUS)  // 110
#define NTHREADS 256
#define NWARPS   8
#define GRIDSZ   (3 * 5 * BATCH)    // 480 blocks

// NOTE: no static initializers — uninitialized __device__ globals are
// zero-filled at module load, and the last finishing block re-zeros them
// so every graph replay starts from the same state.
__device__ double             g_sum;
__device__ unsigned long long g_cnt;
__device__ unsigned int       g_done;

__global__ __launch_bounds__(NTHREADS)
void boundary_loss_kernel(const float* __restrict__ logits,
                          const int*   __restrict__ labels,
                          float*       __restrict__ out) {
    // raw masks (full 11 words): b1 = (lbl==1), inb = in-bounds pixel
    __shared__ uint32_t sB1 [IN_ROWS][IN_WORDS];
    __shared__ uint32_t sINB[IN_ROWS][IN_WORDS];
    // ok = (lbl==0 || lbl==1)  (payload words only)
    __shared__ uint32_t sOK [IN_ROWS][PW];
    // h-spread masks (payload words); becomes GW PREFIX in place
    __shared__ uint32_t sHa [2][IN_ROWS][PW];
    // GW suffix
    __shared__ uint32_t sSuf[2][IN_ROWS][PW];
    // final 15x15-window valid mask per output row
    __shared__ uint32_t sValid[TY][PW];
    __shared__ float    sPartS[NWARPS];
    __shared__ unsigned sPartC[NWARPS];

    const int b    = blockIdx.z;
    const int x0   = blockIdx.x * TX;
    const int y0   = blockIdx.y * TY;
    const int tid  = threadIdx.x;
    const int lane = tid & 31;
    const int warp = tid >> 5;
    const int baseCol = x0 - 32;

    // ------------- Phase 1: pack labels into bit masks ----------------------
    // One warp packs one (row, word): coalesced 32-int load + 3 ballots.
    // Halo words (wi==0 / wi==10) only need 7 boundary bits -> predicate the
    // load to the lanes that matter (touches 1 sector instead of 4).
    {
        int ir = 0, wi = warp;            // t = ir*11 + wi, stepping by NWARPS
        while (ir < IN_ROWS) {
            const int y   = y0 - RADIUS + ir;
            const int col = baseCol + (wi << 5) + lane;
            bool want = true;
            if (wi == 0)             want = (lane >= 32 - RADIUS);
            else if (wi == IN_WORDS - 1) want = (lane < RADIUS);
            int lbl = -1;
            if (want && (unsigned)y < (unsigned)HH && (unsigned)col < (unsigned)WW)
                lbl = labels[(b * HH + y) * WW + col];
            const unsigned m1  = __ballot_sync(0xffffffffu, lbl == 1);
            const unsigned inb = __ballot_sync(0xffffffffu, lbl >= 0);
            const unsigned okb = __ballot_sync(0xffffffffu, lbl == 0 || lbl == 1);
            if (lane == 0) {
                sB1 [ir][wi] = m1;
                sINB[ir][wi] = inb;
                if (wi >= 1 && wi <= PW) sOK[ir][wi - 1] = okb;
            }
            wi += NWARPS;
            if (wi >= IN_WORDS) { wi -= IN_WORDS; ir += 1; }
        }
    }
    __syncthreads();

    // ------------- Phase 2: horizontal radius-7 OR (log-doubling) -----------
    // 220 tasks: (row, mask). mask1 = spread(b1); mask0 = spread(inb & ~b1).
    if (tid < IN_ROWS * 2) {
        const int ir = tid >> 1;
        const int mk = tid & 1;
        uint32_t m[IN_WORDS];
        if (mk) {
            #pragma unroll
            for (int i = 0; i < IN_WORDS; i++) m[i] = sB1[ir][i];
        } else {
            #pragma unroll
            for (int i = 0; i < IN_WORDS; i++) m[i] = sINB[ir][i] & ~sB1[ir][i];
        }
        #pragma unroll
        for (int s = 0; s < 3; s++) {
            const int d = 1 << s;           // 1,2,4 -> cumulative radius 7
            uint32_t t2[IN_WORDS];
            #pragma unroll
            for (int i = 0; i < IN_WORDS; i++) {
                uint32_t lo = (i > 0)            ? m[i - 1] : 0u;
                uint32_t hi = (i < IN_WORDS - 1) ? m[i + 1] : 0u;
                t2[i] = m[i]
                      | (m[i] << d) | (lo >> (32 - d))
                      | (m[i] >> d) | (hi << (32 - d));
            }
            #pragma unroll
            for (int i = 0; i < IN_WORDS; i++) m[i] = t2[i];
        }
        #pragma unroll
        for (int i = 0; i < PW; i++) sHa[mk][ir][i] = m[i + 1];
    }
    __syncthreads();

    // ------------- Phase 3: vertical GW prefix/suffix (chunk = 15 rows) -----
    // 144 tasks: (mask, chunk, word). Suffix into sSuf, prefix in place in sHa.
    {
        const int NCHUNK = (IN_ROWS + 14) / 15;   // 8
        if (tid < 2 * NCHUNK * PW) {
            const int mk  = tid / (NCHUNK * PW);
            const int rem = tid - mk * (NCHUNK * PW);
            const int c   = rem / PW;
            const int wi  = rem - c * PW;
            const int first = c * 15;
            const int last  = min(first + 14, IN_ROWS - 1);
            uint32_t v = sHa[mk][last][wi];
            sSuf[mk][last][wi] = v;
            for (int i = last - 1; i >= first; i--) {
                v |= sHa[mk][i][wi];
                sSuf[mk][i][wi] = v;
            }
            uint32_t p = sHa[mk][first][wi];
            for (int i = first + 1; i <= last; i++) {
                p |= sHa[mk][i][wi];
                sHa[mk][i][wi] = p;
            }
        }
    }
    __syncthreads();

    // ------------- Phase 4: combine -> valid mask per output row ------------
    // valid[r] = (OR rows r..r+14 of mask1) & (same for mask0)
    for (int t = tid; t < TY * PW; t += NTHREADS) {
        const int r  = t / PW;
        const int wi = t - r * PW;
        const uint32_t v1 = sSuf[1][r][wi] | sHa[1][r + 14][wi];
        const uint32_t v0 = sSuf[0][r][wi] | sHa[0][r + 14][wi];
        sValid[r][wi] = v0 & v1;
    }
    __syncthreads();

    // ------------- Phase 5: gather + reduce ---------------------------------
    // Tiles divide H and W exactly -> no bounds checks here.
    float    fsum = 0.0f;
    unsigned fcnt = 0u;
    for (int r = warp; r < TY; r += NWARPS) {
        const int y = y0 + r;
        const float* __restrict__ pbase =
            logits + ((size_t)(b * CH) * HH + y) * WW + x0 + lane;
        #pragma unroll
        for (int wi = 0; wi < PW; wi++) {
            const uint32_t okm = sValid[r][wi] & sOK[r + RADIUS][wi];
            if ((okm >> lane) & 1u) {
                const uint32_t lb = (sB1[r + RADIUS][wi + 1] >> lane) & 1u;
                fsum += pbase[(wi << 5) + (lb ? HWPLANE : 0)];
                fcnt += 1u;
            }
        }
    }

    #pragma unroll
    for (int o = 16; o > 0; o >>= 1) {
        fsum += __shfl_down_sync(0xffffffffu, fsum, o);
        fcnt += __shfl_down_sync(0xffffffffu, fcnt, o);
    }
    if (lane == 0) { sPartS[warp] = fsum; sPartC[warp] = fcnt; }
    __syncthreads();

    if (tid == 0) {
        double s = 0.0;
        unsigned long long c = 0ULL;
        #pragma unroll
        for (int i = 0; i < NWARPS; i++) { s += (double)sPartS[i]; c += sPartC[i]; }
        atomicAdd(&g_sum, s);
        atomicAdd(&g_cnt, c);
        __threadfence();
        const unsigned old = atomicAdd(&g_done, 1u);
        if (old == GRIDSZ - 1) {
            // last block: finalize and reset globals (graph-replay determinism)
            const double ts = atomicAdd(&g_sum, 0.0);
            unsigned long long tc = atomicAdd(&g_cnt, 0ULL);
            if (tc == 0ULL) tc = 1ULL;
            out[0] = (float)(-ts / (double)tc);
            g_sum  = 0.0;
            g_cnt  = 0ULL;
            g_done = 0u;
        }
    }
}

extern "C" void kernel_launch(void* const* d_in, const int* in_sizes, int n_in,
                              void* d_out, int out_size) {
    const float* logits = (const float*)d_in[0];
    const int*   labels = (const int*)d_in[1];
    float*       out    = (float*)d_out;

    dim3 grid(WW / TX,   // 3
              HH / TY,   // 5
              BATCH);    // 32  -> 480 blocks
    boundary_loss_kernel<<<grid, NTHREADS>>>(logits, labels, out);
}

// round 4
// speedup vs baseline: 2.1986x; 2.1986x over previous
#include <cuda_runtime.h>
#include <cstdint>

// Problem constants (fixed by setup_inputs)
#define BATCH    32
#define CH       2
#define HH       480
#define WW       864
#define HWPLANE  (HH * WW)          // 414720

#define RADIUS   7
#define TX       288                // 9 payload words, W = 3 tiles exactly
#define TY       48                 // H = 10 tiles exactly
#define PW       9                  // payload words
#define IN_WORDS 11                 // 1 halo word each side
#define IN_ROWS  (TY + 2 * RADIUS)  // 62
#define NTHREADS 256
#define NWARPS   8
#define GRIDSZ   (3 * 10 * BATCH)   // 960 blocks

__device__ double             g_sum;
__device__ unsigned long long g_cnt;
__device__ unsigned int       g_done;

__global__ __launch_bounds__(NTHREADS)
void boundary_loss_kernel(const float* __restrict__ logits,
                          const int*   __restrict__ labels,
                          float*       __restrict__ out) {
    __shared__ uint32_t sB1[IN_ROWS][IN_WORDS];   // raw (lbl==1) bits
    __shared__ uint32_t sM0[IN_ROWS][IN_WORDS];   // raw (lbl==0 || lbl==255) bits
    __shared__ uint32_t sOK[TY][PW];              // (lbl==0||lbl==1), output rows only
    __shared__ uint32_t sA [2][IN_ROWS][PW];      // ping
    __shared__ uint32_t sBuf[2][IN_ROWS][PW];     // pong
    __shared__ uint32_t sValid[TY][PW];
    __shared__ float    sPartS[NWARPS];
    __shared__ unsigned sPartC[NWARPS];

    const int b    = blockIdx.z;
    const int x0   = blockIdx.x * TX;
    const int y0   = blockIdx.y * TY;
    const int tid  = threadIdx.x;
    const int lane = tid & 31;
    const int warp = tid >> 5;
    const int baseCol = x0 - 32;

    // ---------------- Phase 1: pack labels (batched loads, MLP=11) ----------
    for (int ir = warp; ir < IN_ROWS; ir += NWARPS) {
        const int y   = y0 - RADIUS + ir;
        const bool yok = (unsigned)y < (unsigned)HH;
        const int* __restrict__ rowp = labels + ((size_t)b * HH + y) * WW + baseCol;
        int lbl[IN_WORDS];
        #pragma unroll
        for (int wi = 0; wi < IN_WORDS; wi++) {
            const int c   = (wi << 5) + lane;
            const int col = baseCol + c;
            bool want = yok && (unsigned)col < (unsigned)WW;
            if (wi == 0)              want = want && (lane >= 32 - RADIUS);
            if (wi == IN_WORDS - 1)   want = want && (lane < RADIUS);
            lbl[wi] = want ? rowp[c] : -1;          // 11 independent LDGs
        }
        #pragma unroll
        for (int wi = 0; wi < IN_WORDS; wi++) {
            const unsigned b1   = __ballot_sync(0xffffffffu, lbl[wi] == 1);
            const unsigned b0   = __ballot_sync(0xffffffffu, lbl[wi] == 0);
            const unsigned b255 = __ballot_sync(0xffffffffu, lbl[wi] == 255);
            if (lane == 0) {
                sB1[ir][wi] = b1;
                sM0[ir][wi] = b0 | b255;
                if (wi >= 1 && wi <= PW && ir >= RADIUS && ir < RADIUS + TY)
                    sOK[ir - RADIUS][wi - 1] = b0 | b1;
            }
        }
    }
    __syncthreads();

    // ------------- Phase 2: horizontal radius-7 OR (per row-word task) ------
    // 2*62*9 = 1116 tasks; each does a 3-word register-window log-doubling.
    for (int t = tid; t < 2 * IN_ROWS * PW; t += NTHREADS) {
        const int mk  = t / (IN_ROWS * PW);
        const int rem = t - mk * (IN_ROWS * PW);
        const int ir  = rem / PW;
        const int wi  = rem - ir * PW;
        uint32_t L, M, R;
        if (mk) { L = sB1[ir][wi]; M = sB1[ir][wi+1]; R = sB1[ir][wi+2]; }
        else    { L = sM0[ir][wi]; M = sM0[ir][wi+1]; R = sM0[ir][wi+2]; }
        #pragma unroll
        for (int s = 0; s < 3; s++) {
            const int d = 1 << s;              // 1,2,4 -> radius 7
            const uint32_t nL = L | (L << d) | (L >> d) | (M << (32 - d));
            const uint32_t nM = M | (M << d) | (L >> (32 - d))
                                  | (M >> d) | (R << (32 - d));
            const uint32_t nR = R | (R << d) | (M >> (32 - d)) | (R >> d);
            L = nL; M = nM; R = nR;
        }
        sA[mk][ir][wi] = M;
    }
    __syncthreads();

    // ------------- Phase 3: vertical 15-row OR via log-doubling -------------
    // p2: rows 0..60   (sA -> sBuf)
    for (int t = tid; t < 2 * (IN_ROWS - 1) * PW; t += NTHREADS) {
        const int mk  = t / ((IN_ROWS - 1) * PW);
        const int rem = t - mk * ((IN_ROWS - 1) * PW);
        const int r   = rem / PW;
        const int wi  = rem - r * PW;
        sBuf[mk][r][wi] = sA[mk][r][wi] | sA[mk][r + 1][wi];
    }
    __syncthreads();
    // p4: rows 0..58   (sBuf -> sA)
    for (int t = tid; t < 2 * (IN_ROWS - 3) * PW; t += NTHREADS) {
        const int mk  = t / ((IN_ROWS - 3) * PW);
        const int rem = t - mk * ((IN_ROWS - 3) * PW);
        const int r   = rem / PW;
        const int wi  = rem - r * PW;
        sA[mk][r][wi] = sBuf[mk][r][wi] | sBuf[mk][r + 2][wi];
    }
    __syncthreads();
    // p8: rows 0..54   (sA -> sBuf)
    for (int t = tid; t < 2 * (IN_ROWS - 7) * PW; t += NTHREADS) {
        const int mk  = t / ((IN_ROWS - 7) * PW);
        const int rem = t - mk * ((IN_ROWS - 7) * PW);
        const int r   = rem / PW;
        const int wi  = rem - r * PW;
        sBuf[mk][r][wi] = sA[mk][r][wi] | sA[mk][r + 4][wi];
    }
    __syncthreads();
    // or15[r] = p8[r] | p8[r+7], then valid = or15_0 & or15_1
    for (int t = tid; t < TY * PW; t += NTHREADS) {
        const int r  = t / PW;
        const int wi = t - r * PW;
        const uint32_t v1 = sBuf[1][r][wi] | sBuf[1][r + 7][wi];
        const uint32_t v0 = sBuf[0][r][wi] | sBuf[0][r + 7][wi];
        sValid[r][wi] = v0 & v1;
    }
    __syncthreads();

    // ------------- Phase 4: gather + reduce ---------------------------------
    float    fsum = 0.0f;
    unsigned fcnt = 0u;
    for (int r = warp; r < TY; r += NWARPS) {
        const int y = y0 + r;
        const float* __restrict__ pbase =
            logits + ((size_t)(b * CH) * HH + y) * WW + x0 + lane;
        #pragma unroll
        for (int wi = 0; wi < PW; wi++) {
            const uint32_t okm = sValid[r][wi] & sOK[r][wi];
            if ((okm >> lane) & 1u) {
                const uint32_t lb = (sB1[r + RADIUS][wi + 1] >> lane) & 1u;
                fsum += pbase[(wi << 5) + (lb ? HWPLANE : 0)];
                fcnt += 1u;
            }
        }
    }

    #pragma unroll
    for (int o = 16; o > 0; o >>= 1) {
        fsum += __shfl_down_sync(0xffffffffu, fsum, o);
        fcnt += __shfl_down_sync(0xffffffffu, fcnt, o);
    }
    if (lane == 0) { sPartS[warp] = fsum; sPartC[warp] = fcnt; }
    __syncthreads();

    if (tid == 0) {
        double s = 0.0;
        unsigned long long c = 0ULL;
        #pragma unroll
        for (int i = 0; i < NWARPS; i++) { s += (double)sPartS[i]; c += sPartC[i]; }
        atomicAdd(&g_sum, s);
        atomicAdd(&g_cnt, c);
        __threadfence();
        const unsigned old = atomicAdd(&g_done, 1u);
        if (old == GRIDSZ - 1) {
            const double ts = atomicAdd(&g_sum, 0.0);
            unsigned long long tc = atomicAdd(&g_cnt, 0ULL);
            if (tc == 0ULL) tc = 1ULL;
            out[0] = (float)(-ts / (double)tc);
            g_sum  = 0.0;
            g_cnt  = 0ULL;
            g_done = 0u;
        }
    }
}

extern "C" void kernel_launch(void* const* d_in, const int* in_sizes, int n_in,
                              void* d_out, int out_size) {
    const float* logits = (const float*)d_in[0];
    const int*   labels = (const int*)d_in[1];
    float*       out    = (float*)d_out;

    dim3 grid(WW / TX,   // 3
              HH / TY,   // 10
              BATCH);    // 32  -> 960 blocks
    boundary_loss_kernel<<<grid, NTHREADS>>>(logits, labels, out);
}

// round 5
// speedup vs baseline: 2.6150x; 1.1894x over previous
#include <cuda_runtime.h>
#include <cstdint>

// Problem constants (fixed by setup_inputs)
#define BATCH    32
#define CH       2
#define HH       480
#define WW       864
#define HWPLANE  (HH * WW)          // 414720

#define RADIUS   7
#define TX       288                // 9 payload words, W = 3 tiles exactly
#define TY       40                 // H = 12 tiles exactly
#define PW       9                  // payload words
#define IN_WORDS 11                 // 1 halo word each side
#define IN_ROWS  (TY + 2 * RADIUS)  // 54
#define NTHREADS 256
#define NWARPS   8
#define GRIDSZ   (3 * 12 * BATCH)   // 1152 blocks

__device__ double             g_sum;
__device__ unsigned long long g_cnt;
__device__ unsigned int       g_done;

__global__ __launch_bounds__(NTHREADS)
void boundary_loss_kernel(const float* __restrict__ logits,
                          const int*   __restrict__ labels,
                          float*       __restrict__ out) {
    __shared__ uint32_t sB1 [IN_ROWS][IN_WORDS];  // raw (lbl==1) bits
    __shared__ uint32_t sM0 [IN_ROWS][IN_WORDS];  // raw (lbl==0 || lbl==255) bits
    __shared__ uint32_t sOK [TY][PW];             // (lbl valid target), output rows
    __shared__ uint32_t sA  [2][IN_ROWS][PW];     // ping
    __shared__ uint32_t sBuf[2][IN_ROWS][PW];     // pong
    __shared__ uint32_t sValid[TY][PW];           // final okm = valid & ok
    __shared__ float    sPartS[NWARPS];
    __shared__ unsigned sPartC[NWARPS];

    const int b    = blockIdx.z;
    const int x0   = blockIdx.x * TX;
    const int y0   = blockIdx.y * TY;
    const int tid  = threadIdx.x;
    const int lane = tid & 31;
    const int warp = tid >> 5;
    const int baseCol = x0 - 32;

    // Constant in-bounds masks for halo words (x-direction).
    const uint32_t inbW0  = (x0 > 0)           ? 0xFE000000u : 0u;  // lanes 25..31
    const uint32_t inbW10 = (x0 + TX < WW)     ? 0x0000007Fu : 0u;  // lanes 0..6

    // ---------------- Phase 1: pack labels (batched loads, MLP=11) ----------
    for (int ir = warp; ir < IN_ROWS; ir += NWARPS) {
        const int y    = y0 - RADIUS + ir;
        const bool yok = (unsigned)y < (unsigned)HH;
        const int* __restrict__ rowp = labels + ((size_t)b * HH + y) * WW + baseCol;
        int lbl[IN_WORDS];
        #pragma unroll
        for (int wi = 0; wi < IN_WORDS; wi++) {
            const uint32_t inbc = (wi == 0) ? inbW0
                                : (wi == IN_WORDS - 1) ? inbW10 : 0xFFFFFFFFu;
            const bool want = yok && ((inbc >> lane) & 1u);
            lbl[wi] = want ? rowp[(wi << 5) + lane] : -1;   // 11 independent LDGs
        }
        const bool outRow = (ir >= RADIUS) && (ir < RADIUS + TY);
        #pragma unroll
        for (int wi = 0; wi < IN_WORDS; wi++) {
            const uint32_t inbc = (wi == 0) ? inbW0
                                : (wi == IN_WORDS - 1) ? inbW10 : 0xFFFFFFFFu;
            const uint32_t inb  = yok ? inbc : 0u;
            const unsigned m1   = __ballot_sync(0xffffffffu, lbl[wi] == 1);
            const unsigned m255 = __ballot_sync(0xffffffffu, lbl[wi] == 255);
            if (lane == 0) {
                sB1[ir][wi] = m1;
                sM0[ir][wi] = inb & ~m1;      // lbl in {0,255} (labels are {0,1,IGNORE})
                if (wi >= 1 && wi <= PW && outRow)
                    sOK[ir - RADIUS][wi - 1] = ~m255;   // output rows fully in-bounds
            }
        }
    }
    __syncthreads();

    // ------------- Phase 2: horizontal radius-7 OR (per row-word task) ------
    for (int t = tid; t < 2 * IN_ROWS * PW; t += NTHREADS) {
        const int mk  = t / (IN_ROWS * PW);
        const int rem = t - mk * (IN_ROWS * PW);
        const int ir  = rem / PW;
        const int wi  = rem - ir * PW;
        uint32_t L, M, R;
        if (mk) { L = sB1[ir][wi]; M = sB1[ir][wi+1]; R = sB1[ir][wi+2]; }
        else    { L = sM0[ir][wi]; M = sM0[ir][wi+1]; R = sM0[ir][wi+2]; }
        #pragma unroll
        for (int s = 0; s < 3; s++) {
            const int d = 1 << s;              // 1,2,4 -> radius 7
            const uint32_t nL = L | (L << d) | (L >> d) | (M << (32 - d));
            const uint32_t nM = M | (M << d) | (L >> (32 - d))
                                  | (M >> d) | (R << (32 - d));
            const uint32_t nR = R | (R << d) | (M >> (32 - d)) | (R >> d);
            L = nL; M = nM; R = nR;
        }
        sA[mk][ir][wi] = M;
    }
    __syncthreads();

    // ------------- Phase 3: vertical 15-row OR via log-doubling -------------
    // p2: rows 0..IN_ROWS-2
    for (int t = tid; t < 2 * (IN_ROWS - 1) * PW; t += NTHREADS) {
        const int mk  = t / ((IN_ROWS - 1) * PW);
        const int rem = t - mk * ((IN_ROWS - 1) * PW);
        const int r   = rem / PW;
        const int wi  = rem - r * PW;
        sBuf[mk][r][wi] = sA[mk][r][wi] | sA[mk][r + 1][wi];
    }
    __syncthreads();
    // p4: rows 0..IN_ROWS-4
    for (int t = tid; t < 2 * (IN_ROWS - 3) * PW; t += NTHREADS) {
        const int mk  = t / ((IN_ROWS - 3) * PW);
        const int rem = t - mk * ((IN_ROWS - 3) * PW);
        const int r   = rem / PW;
        const int wi  = rem - r * PW;
        sA[mk][r][wi] = sBuf[mk][r][wi] | sBuf[mk][r + 2][wi];
    }
    __syncthreads();
    // p8: rows 0..IN_ROWS-8
    for (int t = tid; t < 2 * (IN_ROWS - 7) * PW; t += NTHREADS) {
        const int mk  = t / ((IN_ROWS - 7) * PW);
        const int rem = t - mk * ((IN_ROWS - 7) * PW);
        const int r   = rem / PW;
        const int wi  = rem - r * PW;
        sBuf[mk][r][wi] = sA[mk][r][wi] | sA[mk][r + 4][wi];
    }
    __syncthreads();
    // or15[r] = p8[r] | p8[r+7]; fold OK here -> one LDS fewer in gather
    for (int t = tid; t < TY * PW; t += NTHREADS) {
        const int r  = t / PW;
        const int wi = t - r * PW;
        const uint32_t v1 = sBuf[1][r][wi] | sBuf[1][r + 7][wi];
        const uint32_t v0 = sBuf[0][r][wi] | sBuf[0][r + 7][wi];
        sValid[r][wi] = v0 & v1 & sOK[r][wi];
    }
    __syncthreads();

    // ------------- Phase 4: gather + reduce ---------------------------------
    float    fsum = 0.0f;
    unsigned wcnt = 0u;                       // warp-uniform count via popc
    for (int r = warp; r < TY; r += NWARPS) {
        const int y = y0 + r;
        const float* __restrict__ pbase =
            logits + ((size_t)(b * CH) * HH + y) * WW + x0 + lane;
        #pragma unroll
        for (int wi = 0; wi < PW; wi++) {
            const uint32_t okm = sValid[r][wi];
            wcnt += __popc(okm);
            if ((okm >> lane) & 1u) {
                const uint32_t lb = (sB1[r + RADIUS][wi + 1] >> lane) & 1u;
                fsum += pbase[(wi << 5) + (lb ? HWPLANE : 0)];
            }
        }
    }

    #pragma unroll
    for (int o = 16; o > 0; o >>= 1)
        fsum += __shfl_down_sync(0xffffffffu, fsum, o);
    if (lane == 0) { sPartS[warp] = fsum; sPartC[warp] = wcnt; }
    __syncthreads();

    if (tid == 0) {
        double s = 0.0;
        unsigned long long c = 0ULL;
        #pragma unroll
        for (int i = 0; i < NWARPS; i++) { s += (double)sPartS[i]; c += sPartC[i]; }
        atomicAdd(&g_sum, s);
        atomicAdd(&g_cnt, c);
        __threadfence();
        const unsigned old = atomicAdd(&g_done, 1u);
        if (old == GRIDSZ - 1) {
            const double ts = atomicAdd(&g_sum, 0.0);
            unsigned long long tc = atomicAdd(&g_cnt, 0ULL);
            if (tc == 0ULL) tc = 1ULL;
            out[0] = (float)(-ts / (double)tc);
            g_sum  = 0.0;
            g_cnt  = 0ULL;
            g_done = 0u;
        }
    }
}

extern "C" void kernel_launch(void* const* d_in, const int* in_sizes, int n_in,
                              void* d_out, int out_size) {
    const float* logits = (const float*)d_in[0];
    const int*   labels = (const int*)d_in[1];
    float*       out    = (float*)d_out;

    dim3 grid(WW / TX,   // 3
              HH / TY,   // 12
              BATCH);    // 32  -> 1152 blocks
    boundary_loss_kernel<<<grid, NTHREADS>>>(logits, labels, out);
}